// round 11
// baseline (speedup 1.0000x reference)
#include <cuda_runtime.h>
#include <cuda_bf16.h>
#include <cstdint>

#define B_   2
#define T_   4096
#define D_   768
#define H_   12
#define HD_  64
#define SCALE_ 0.125f

#define QT 256
#define KT 64

// ---------------- scratch ----------------
__device__ __nv_bfloat16 g_qh[(size_t)B_ * H_ * T_ * HD_];   // [B,H,T,hd]
__device__ __nv_bfloat16 g_ql[(size_t)B_ * H_ * T_ * HD_];
__device__ __nv_bfloat16 g_kh[(size_t)B_ * H_ * T_ * HD_];
__device__ __nv_bfloat16 g_kl[(size_t)B_ * H_ * T_ * HD_];
__device__ __nv_bfloat16 g_vh[(size_t)B_ * H_ * T_ * HD_];   // TRANSPOSED: [B,H,hd,T]
__device__ __nv_bfloat16 g_vl[(size_t)B_ * H_ * T_ * HD_];
__device__ __nv_bfloat16 g_xh[(size_t)B_ * T_ * D_];
__device__ __nv_bfloat16 g_xl[(size_t)B_ * T_ * D_];
__device__ __nv_bfloat16 g_ah[(size_t)B_ * T_ * D_];
__device__ __nv_bfloat16 g_al[(size_t)B_ * T_ * D_];
__device__ __nv_bfloat16 g_wqh[(size_t)3 * D_ * D_];
__device__ __nv_bfloat16 g_wql[(size_t)3 * D_ * D_];
__device__ __nv_bfloat16 g_woh[(size_t)D_ * D_];
__device__ __nv_bfloat16 g_wol[(size_t)D_ * D_];

// ======================= helpers ========================
__device__ __forceinline__ uint32_t smem_u32(const void* p) {
    uint32_t a;
    asm("{ .reg .u64 t; cvta.to.shared.u64 t, %1; cvt.u32.u64 %0, t; }"
        : "=r"(a) : "l"(p));
    return a;
}

__device__ __forceinline__ void cp16(uint32_t s, const void* g) {
    asm volatile("cp.async.cg.shared.global [%0], [%1], 16;" :: "r"(s), "l"(g));
}
#define CP_COMMIT() asm volatile("cp.async.commit_group;" ::: "memory")
#define CP_WAIT1()  asm volatile("cp.async.wait_group 1;" ::: "memory")
#define CP_WAIT0()  asm volatile("cp.async.wait_group 0;" ::: "memory")

__device__ __forceinline__ void mma16816(float* c, const uint32_t* a, const uint32_t* b) {
    asm("mma.sync.aligned.m16n8k16.row.col.f32.bf16.bf16.f32 "
        "{%0,%1,%2,%3}, {%4,%5,%6,%7}, {%8,%9}, {%0,%1,%2,%3};"
        : "+f"(c[0]), "+f"(c[1]), "+f"(c[2]), "+f"(c[3])
        : "r"(a[0]), "r"(a[1]), "r"(a[2]), "r"(a[3]), "r"(b[0]), "r"(b[1]));
}

__device__ __forceinline__ uint32_t pack_bf(__nv_bfloat16 a, __nv_bfloat16 b) {
    __nv_bfloat162 t(a, b);
    return *reinterpret_cast<uint32_t*>(&t);
}

__device__ __forceinline__ void split2(float v0, float v1, uint32_t& hi, uint32_t& lo) {
    __nv_bfloat16 h0 = __float2bfloat16_rn(v0);
    __nv_bfloat16 h1 = __float2bfloat16_rn(v1);
    float r0 = v0 - __bfloat162float(h0);
    float r1 = v1 - __bfloat162float(h1);
    hi = pack_bf(h0, h1);
    lo = pack_bf(__float2bfloat16_rn(r0), __float2bfloat16_rn(r1));
}

// ======================================================================
// conversions
// ======================================================================
__global__ void conv_split(const float* __restrict__ in,
                           __nv_bfloat16* __restrict__ oh,
                           __nv_bfloat16* __restrict__ ol, int n)
{
    int i = blockIdx.x * blockDim.x + threadIdx.x;
    if (i >= n) return;
    float v = in[i];
    __nv_bfloat16 h = __float2bfloat16_rn(v);
    float r = v - __bfloat162float(h);
    oh[i] = h;
    ol[i] = __float2bfloat16_rn(r);
}

__global__ void conv_split_tr(const float* __restrict__ in,
                              __nv_bfloat16* __restrict__ oh,
                              __nv_bfloat16* __restrict__ ol, int K, int N)
{
    int i = blockIdx.x * blockDim.x + threadIdx.x;
    if (i >= K * N) return;
    int k = i / N, n = i % N;
    float v = in[i];
    __nv_bfloat16 h = __float2bfloat16_rn(v);
    float r = v - __bfloat162float(h);
    oh[(size_t)n * K + k] = h;
    ol[(size_t)n * K + k] = __float2bfloat16_rn(r);
}

// ======================================================================
// HMMA GEMM, bf16 split. Block tile 128(M)x256(N), 256 threads, 8 warps
// in 2(M)x4(N), warp tile 64x64. (unchanged from round 10 passing version)
// ======================================================================
#define LDKB 144
#define ATILE (128 * LDKB)
#define BTILE (256 * LDKB)
#define BUFSZ (2 * ATILE + 2 * BTILE)
#define AOFF(buf, v) ((buf) * BUFSZ + (v) * ATILE)
#define BOFF(buf, v) ((buf) * BUFSZ + 2 * ATILE + (v) * BTILE)
#define SMEM_GT (2 * BUFSZ)

__global__ void __launch_bounds__(256, 1) gemm_tc_mma(
    const __nv_bfloat16* __restrict__ Ah, const __nv_bfloat16* __restrict__ Al,
    const __nv_bfloat16* __restrict__ Bh, const __nv_bfloat16* __restrict__ Bl,
    const float* __restrict__ bias, float* __restrict__ Cout,
    int M, int N, int K, int mode)
{
    extern __shared__ char smc[];
    const uint32_t sbase = smem_u32(smc);
    const int tid  = threadIdx.x;
    const int lane = tid & 31;
    const int wid  = tid >> 5;
    const int wm   = wid & 1;
    const int wn   = wid >> 1;
    const int bm = blockIdx.y * 128;
    const int bn = blockIdx.x * 256;

    const char* gA[2] = { (const char*)(Ah + (size_t)bm * K),
                          (const char*)(Al + (size_t)bm * K) };
    const char* gB[2] = { (const char*)(Bh + (size_t)bn * K),
                          (const char*)(Bl + (size_t)bn * K) };

    const int nk = K / 64;

    auto issue_chunk = [&](int k0, int buf) {
#pragma unroll
        for (int v = 0; v < 2; v++) {
#pragma unroll
            for (int j = 0; j < 4; j++) {
                const int idx = j * 256 + tid;
                const int row = idx >> 3, c16 = idx & 7;
                cp16(sbase + AOFF(buf, v) + row * LDKB + c16 * 16,
                     gA[v] + (size_t)row * (K * 2) + k0 * 2 + c16 * 16);
            }
#pragma unroll
            for (int j = 0; j < 8; j++) {
                const int idx = j * 256 + tid;
                const int row = idx >> 3, c16 = idx & 7;
                cp16(sbase + BOFF(buf, v) + row * LDKB + c16 * 16,
                     gB[v] + (size_t)row * (K * 2) + k0 * 2 + c16 * 16);
            }
        }
    };

    issue_chunk(0, 0); CP_COMMIT();
    if (nk > 1) { issue_chunk(64, 1); }
    CP_COMMIT();

    float acc[4][8][4];
#pragma unroll
    for (int i = 0; i < 4; i++)
#pragma unroll
        for (int j = 0; j < 8; j++)
#pragma unroll
            for (int q = 0; q < 4; q++) acc[i][j][q] = 0.f;

    const int lr = lane >> 2;
    const int lc = (lane & 3) * 2;

    for (int it = 0; it < nk; ++it) {
        const int buf = it & 1;
        CP_WAIT1();
        __syncthreads();

        const char* sA[2] = { smc + AOFF(buf, 0), smc + AOFF(buf, 1) };
        const char* sB[2] = { smc + BOFF(buf, 0), smc + BOFF(buf, 1) };

#pragma unroll
        for (int kk = 0; kk < 4; kk++) {
            const int kb = kk * 32 + lc * 2;
            uint32_t af[2][4][4];
#pragma unroll
            for (int v = 0; v < 2; v++)
#pragma unroll
                for (int i = 0; i < 4; i++) {
                    const int r0 = (wm * 64 + i * 16 + lr) * LDKB;
                    af[v][i][0] = *(const uint32_t*)(sA[v] + r0 + kb);
                    af[v][i][1] = *(const uint32_t*)(sA[v] + r0 + 8 * LDKB + kb);
                    af[v][i][2] = *(const uint32_t*)(sA[v] + r0 + kb + 16);
                    af[v][i][3] = *(const uint32_t*)(sA[v] + r0 + 8 * LDKB + kb + 16);
                }
            uint32_t bf[2][8][2];
#pragma unroll
            for (int v = 0; v < 2; v++)
#pragma unroll
                for (int j = 0; j < 8; j++) {
                    const int n0 = (wn * 64 + j * 8 + lr) * LDKB;
                    bf[v][j][0] = *(const uint32_t*)(sB[v] + n0 + kb);
                    bf[v][j][1] = *(const uint32_t*)(sB[v] + n0 + kb + 16);
                }
#pragma unroll
            for (int i = 0; i < 4; i++)
#pragma unroll
                for (int j = 0; j < 8; j++)
                    mma16816(acc[i][j], af[0][i], bf[0][j]);
#pragma unroll
            for (int i = 0; i < 4; i++)
#pragma unroll
                for (int j = 0; j < 8; j++)
                    mma16816(acc[i][j], af[0][i], bf[1][j]);
#pragma unroll
            for (int i = 0; i < 4; i++)
#pragma unroll
                for (int j = 0; j < 8; j++)
                    mma16816(acc[i][j], af[1][i], bf[0][j]);
        }
        __syncthreads();
        if (it + 2 < nk) { issue_chunk((it + 2) * 64, buf); }
        CP_COMMIT();
    }

    // -------- epilogue --------
#pragma unroll
    for (int i = 0; i < 4; i++) {
        const int row0 = bm + wm * 64 + i * 16 + lr;
#pragma unroll
        for (int j = 0; j < 8; j++) {
            const int col = bn + wn * 64 + j * 8 + lc;
            const float b0 = bias[col], b1 = bias[col + 1];
            const float v00 = acc[i][j][0] + b0, v01 = acc[i][j][1] + b1;
            const float v10 = acc[i][j][2] + b0, v11 = acc[i][j][3] + b1;
            if (mode == 1) {
                *(float2*)&Cout[(size_t)row0 * N + col]       = make_float2(v00, v01);
                *(float2*)&Cout[(size_t)(row0 + 8) * N + col] = make_float2(v10, v11);
            } else {
                const int sel = col / D_;
                const int rem = col % D_;
                const int h   = rem / HD_;
                const int d0  = rem % HD_;
                const int bb0 = row0 >> 12, t0 = row0 & (T_ - 1);
                const int bb1 = (row0 + 8) >> 12, t1 = (row0 + 8) & (T_ - 1);
                if (sel == 2) {
                    const size_t hb0 = (size_t)(bb0 * H_ + h) * HD_;
                    const size_t hb1 = (size_t)(bb1 * H_ + h) * HD_;
                    __nv_bfloat16 h00 = __float2bfloat16_rn(v00);
                    __nv_bfloat16 h01 = __float2bfloat16_rn(v01);
                    __nv_bfloat16 h10 = __float2bfloat16_rn(v10);
                    __nv_bfloat16 h11 = __float2bfloat16_rn(v11);
                    g_vh[(hb0 + d0)     * T_ + t0] = h00;
                    g_vh[(hb0 + d0 + 1) * T_ + t0] = h01;
                    g_vh[(hb1 + d0)     * T_ + t1] = h10;
                    g_vh[(hb1 + d0 + 1) * T_ + t1] = h11;
                    g_vl[(hb0 + d0)     * T_ + t0] = __float2bfloat16_rn(v00 - __bfloat162float(h00));
                    g_vl[(hb0 + d0 + 1) * T_ + t0] = __float2bfloat16_rn(v01 - __bfloat162float(h01));
                    g_vl[(hb1 + d0)     * T_ + t1] = __float2bfloat16_rn(v10 - __bfloat162float(h10));
                    g_vl[(hb1 + d0 + 1) * T_ + t1] = __float2bfloat16_rn(v11 - __bfloat162float(h11));
                } else {
                    __nv_bfloat16* dh = (sel == 0) ? g_qh : g_kh;
                    __nv_bfloat16* dl = (sel == 0) ? g_ql : g_kl;
                    uint32_t hi, lo;
                    split2(v00, v01, hi, lo);
                    size_t off = ((size_t)(bb0 * H_ + h) * T_ + t0) * HD_ + d0;
                    *(uint32_t*)&dh[off] = hi; *(uint32_t*)&dl[off] = lo;
                    split2(v10, v11, hi, lo);
                    off = ((size_t)(bb1 * H_ + h) * T_ + t1) * HD_ + d0;
                    *(uint32_t*)&dh[off] = hi; *(uint32_t*)&dl[off] = lo;
                }
            }
        }
    }
    CP_WAIT0();
}

// ======================================================================
// Causal flash attention on HMMA. QT=256, warp owns rows {w*16, 128+w*16}
// (interleaved m-tiles -> balanced causal skip). Lazy P-split (no
// persistent P fragment arrays). 3-slot cp.async ring, one sync/tile.
// smem: Q hi/lo 256x144 (73728) + 3 x (K,V hi/lo 64x144 = 36864) = 184320
// ======================================================================
#define APB 144
#define AT_KV  (2 * 256 * APB)           // 73728
#define KVBUF  (4 * 64 * APB)            // 36864 per ring slot
#define SMEM_AT (AT_KV + 3 * KVBUF)      // 184320

__global__ void __launch_bounds__(256, 1) attn_mma()
{
    extern __shared__ char sm[];
    const uint32_t sbase = smem_u32(sm);
    char* sQh = sm;
    char* sQl = sm + 256 * APB;

    const int tid = threadIdx.x, lane = tid & 31, wid = tid >> 5;
    const int lr = lane >> 2, lq = lane & 3;
    const int qi = (int)gridDim.x - 1 - (int)blockIdx.x;
    const int h = blockIdx.y, b = blockIdx.z;
    const int qbase = qi * QT;

    const size_t bh = (size_t)(b * H_ + h) * T_;
    const char* qh = (const char*)(g_qh + (bh + qbase) * HD_);
    const char* ql = (const char*)(g_ql + (bh + qbase) * HD_);
    const char* kh = (const char*)(g_kh + bh * HD_);
    const char* kl = (const char*)(g_kl + bh * HD_);
    const char* vh = (const char*)(g_vh + bh * HD_);   // [hd][T]
    const char* vl = (const char*)(g_vl + bh * HD_);

    auto stage = [&](int kb, int buf) {
        const uint32_t base = sbase + AT_KV + buf * KVBUF;
#pragma unroll
        for (int t = 0; t < 4; t++) {
            const char* src = (t == 0) ? kh : (t == 1) ? kl : (t == 2) ? vh : vl;
#pragma unroll
            for (int j = 0; j < 2; j++) {
                const int idx = j * 256 + tid;
                const int row = idx >> 3, c16 = idx & 7;
                const char* g = (t < 2)
                    ? src + (size_t)(kb + row) * 128 + c16 * 16
                    : src + (size_t)row * (T_ * 2) + (size_t)kb * 2 + c16 * 16;
                cp16(base + t * (64 * APB) + row * APB + c16 * 16, g);
            }
        }
    };

    const int nkt = qbase / KT + 4;

    stage(0, 0); CP_COMMIT();
    stage(KT, 1); CP_COMMIT();

    // stage Q (hi/lo): 256 rows x 128B each
#pragma unroll
    for (int p = 0; p < 8; p++) {
        const int idx = p * 256 + tid;
        const int row = idx >> 3, c16 = idx & 7;
        *(uint4*)(sQh + row * APB + c16 * 16) =
            *(const uint4*)(qh + (size_t)row * 128 + c16 * 16);
        *(uint4*)(sQl + row * APB + c16 * 16) =
            *(const uint4*)(ql + (size_t)row * 128 + c16 * 16);
    }

    float m[2][2], l[2][2];
    float o[2][8][4];
#pragma unroll
    for (int mi = 0; mi < 2; mi++) {
        m[mi][0] = m[mi][1] = -1e30f;
        l[mi][0] = l[mi][1] = 0.f;
#pragma unroll
        for (int j = 0; j < 8; j++)
#pragma unroll
            for (int q = 0; q < 4; q++) o[mi][j][q] = 0.f;
    }

    const int rm0 = qbase + wid * 16 + 15;          // mi=0 rows
    const int rm1 = qbase + 128 + wid * 16 + 15;    // mi=1 rows

    for (int kt = 0; kt < nkt; kt++) {
        const int kb = kt * KT;
        const int buf = kt % 3;
        const char* sKh = sm + AT_KV + buf * KVBUF;
        const char* sKl = sKh + 64 * APB;
        const char* sVh = sKl + 64 * APB;
        const char* sVl = sVh + 64 * APB;

        CP_WAIT1();
        __syncthreads();

        if (kt + 2 < nkt) stage((kt + 2) * KT, (kt + 2) % 3);
        CP_COMMIT();

        if (kb > rm1) continue;              // nothing for this warp
        const bool act0 = (kb <= rm0);       // is the low m-tile active?

        // ---- S = Q K^T ----
        float s[2][8][4];
#pragma unroll
        for (int mi = 0; mi < 2; mi++)
#pragma unroll
            for (int j = 0; j < 8; j++)
#pragma unroll
                for (int q = 0; q < 4; q++) s[mi][j][q] = 0.f;

#pragma unroll
        for (int kk = 0; kk < 4; kk++) {
            const int kbo = kk * 32 + lq * 4;
            uint32_t kf[2][8][2];
#pragma unroll
            for (int j = 0; j < 8; j++) {
                const int n0 = (j * 8 + lr) * APB;
                kf[0][j][0] = *(const uint32_t*)(sKh + n0 + kbo);
                kf[0][j][1] = *(const uint32_t*)(sKh + n0 + kbo + 16);
                kf[1][j][0] = *(const uint32_t*)(sKl + n0 + kbo);
                kf[1][j][1] = *(const uint32_t*)(sKl + n0 + kbo + 16);
            }
            // mi=1 (always active when we got here)
            {
                const int r1 = (128 + wid * 16 + lr) * APB;
                uint32_t qh4[4], ql4[4];
                qh4[0] = *(const uint32_t*)(sQh + r1 + kbo);
                qh4[1] = *(const uint32_t*)(sQh + r1 + 8 * APB + kbo);
                qh4[2] = *(const uint32_t*)(sQh + r1 + kbo + 16);
                qh4[3] = *(const uint32_t*)(sQh + r1 + 8 * APB + kbo + 16);
                ql4[0] = *(const uint32_t*)(sQl + r1 + kbo);
                ql4[1] = *(const uint32_t*)(sQl + r1 + 8 * APB + kbo);
                ql4[2] = *(const uint32_t*)(sQl + r1 + kbo + 16);
                ql4[3] = *(const uint32_t*)(sQl + r1 + 8 * APB + kbo + 16);
#pragma unroll
                for (int j = 0; j < 8; j++) mma16816(s[1][j], qh4, kf[0][j]);
#pragma unroll
                for (int j = 0; j < 8; j++) mma16816(s[1][j], qh4, kf[1][j]);
#pragma unroll
                for (int j = 0; j < 8; j++) mma16816(s[1][j], ql4, kf[0][j]);
            }
            if (act0) {
                const int r0 = (wid * 16 + lr) * APB;
                uint32_t qh4[4], ql4[4];
                qh4[0] = *(const uint32_t*)(sQh + r0 + kbo);
                qh4[1] = *(const uint32_t*)(sQh + r0 + 8 * APB + kbo);
                qh4[2] = *(const uint32_t*)(sQh + r0 + kbo + 16);
                qh4[3] = *(const uint32_t*)(sQh + r0 + 8 * APB + kbo + 16);
                ql4[0] = *(const uint32_t*)(sQl + r0 + kbo);
                ql4[1] = *(const uint32_t*)(sQl + r0 + 8 * APB + kbo);
                ql4[2] = *(const uint32_t*)(sQl + r0 + kbo + 16);
                ql4[3] = *(const uint32_t*)(sQl + r0 + 8 * APB + kbo + 16);
#pragma unroll
                for (int j = 0; j < 8; j++) mma16816(s[0][j], qh4, kf[0][j]);
#pragma unroll
                for (int j = 0; j < 8; j++) mma16816(s[0][j], qh4, kf[1][j]);
#pragma unroll
                for (int j = 0; j < 8; j++) mma16816(s[0][j], ql4, kf[0][j]);
            }
        }

        // ---- scale + causal mask + online softmax, per m-tile ----
#pragma unroll
        for (int mi = 0; mi < 2; mi++) {
            if (mi == 0 && !act0) continue;
            const int mrow = qbase + 128 * mi + wid * 16;
            if (kb + 63 > mrow) {
                const int row_a = mrow + lr;
#pragma unroll
                for (int j = 0; j < 8; j++) {
                    const int col0 = kb + j * 8 + lq * 2;
                    s[mi][j][0] = (col0     <= row_a)     ? s[mi][j][0] * SCALE_ : -1e30f;
                    s[mi][j][1] = (col0 + 1 <= row_a)     ? s[mi][j][1] * SCALE_ : -1e30f;
                    s[mi][j][2] = (col0     <= row_a + 8) ? s[mi][j][2] * SCALE_ : -1e30f;
                    s[mi][j][3] = (col0 + 1 <= row_a + 8) ? s[mi][j][3] * SCALE_ : -1e30f;
                }
            } else {
#pragma unroll
                for (int j = 0; j < 8; j++)
#pragma unroll
                    for (int q = 0; q < 4; q++) s[mi][j][q] *= SCALE_;
            }

#pragma unroll
            for (int r = 0; r < 2; r++) {
                float mx = -1e30f;
#pragma unroll
                for (int j = 0; j < 8; j++)
                    mx = fmaxf(mx, fmaxf(s[mi][j][2 * r], s[mi][j][2 * r + 1]));
                mx = fmaxf(mx, __shfl_xor_sync(0xffffffffu, mx, 1));
                mx = fmaxf(mx, __shfl_xor_sync(0xffffffffu, mx, 2));
                const float mnew = fmaxf(m[mi][r], mx);
                const float corr = __expf(m[mi][r] - mnew);
                float sum = 0.f;
#pragma unroll
                for (int j = 0; j < 8; j++) {
                    const float p0 = __expf(s[mi][j][2 * r]     - mnew);
                    const float p1 = __expf(s[mi][j][2 * r + 1] - mnew);
                    s[mi][j][2 * r] = p0; s[mi][j][2 * r + 1] = p1;
                    sum += p0 + p1;
                }
                sum += __shfl_xor_sync(0xffffffffu, sum, 1);
                sum += __shfl_xor_sync(0xffffffffu, sum, 2);
                l[mi][r] = l[mi][r] * corr + sum;
                m[mi][r] = mnew;
#pragma unroll
                for (int j = 0; j < 8; j++) {
                    o[mi][j][2 * r] *= corr; o[mi][j][2 * r + 1] *= corr;
                }
            }
        }

        // ---- O += P V (lazy P-split: fragments built per kk, no storage) ----
#pragma unroll
        for (int kk = 0; kk < 4; kk++) {
            const int kbo = kk * 32 + lq * 4;
            uint32_t vf[2][8][2];
#pragma unroll
            for (int jn = 0; jn < 8; jn++) {
                const int n0 = (jn * 8 + lr) * APB;
                vf[0][jn][0] = *(const uint32_t*)(sVh + n0 + kbo);
                vf[0][jn][1] = *(const uint32_t*)(sVh + n0 + kbo + 16);
                vf[1][jn][0] = *(const uint32_t*)(sVl + n0 + kbo);
                vf[1][jn][1] = *(const uint32_t*)(sVl + n0 + kbo + 16);
            }
            // mi=1
            {
                uint32_t a_h[4], a_l[4];
                split2(s[1][2 * kk][0],     s[1][2 * kk][1],     a_h[0], a_l[0]);
                split2(s[1][2 * kk][2],     s[1][2 * kk][3],     a_h[1], a_l[1]);
                split2(s[1][2 * kk + 1][0], s[1][2 * kk + 1][1], a_h[2], a_l[2]);
                split2(s[1][2 * kk + 1][2], s[1][2 * kk + 1][3], a_h[3], a_l[3]);
#pragma unroll
                for (int jn = 0; jn < 8; jn++) mma16816(o[1][jn], a_h, vf[0][jn]);
#pragma unroll
                for (int jn = 0; jn < 8; jn++) mma16816(o[1][jn], a_h, vf[1][jn]);
#pragma unroll
                for (int jn = 0; jn < 8; jn++) mma16816(o[1][jn], a_l, vf[0][jn]);
            }
            if (act0) {
                uint32_t a_h[4], a_l[4];
                split2(s[0][2 * kk][0],     s[0][2 * kk][1],     a_h[0], a_l[0]);
                split2(s[0][2 * kk][2],     s[0][2 * kk][3],     a_h[1], a_l[1]);
                split2(s[0][2 * kk + 1][0], s[0][2 * kk + 1][1], a_h[2], a_l[2]);
                split2(s[0][2 * kk + 1][2], s[0][2 * kk + 1][3], a_h[3], a_l[3]);
#pragma unroll
                for (int jn = 0; jn < 8; jn++) mma16816(o[0][jn], a_h, vf[0][jn]);
#pragma unroll
                for (int jn = 0; jn < 8; jn++) mma16816(o[0][jn], a_h, vf[1][jn]);
#pragma unroll
                for (int jn = 0; jn < 8; jn++) mma16816(o[0][jn], a_l, vf[0][jn]);
            }
        }
    }

    // ---- epilogue: normalize, split-write to g_ah/g_al [B,T,D] ----
#pragma unroll
    for (int mi = 0; mi < 2; mi++) {
        const float inv0 = 1.f / l[mi][0], inv1 = 1.f / l[mi][1];
        const int t0 = qbase + 128 * mi + wid * 16 + lr;
        const int t1 = t0 + 8;
#pragma unroll
        for (int jn = 0; jn < 8; jn++) {
            const int d = h * HD_ + jn * 8 + lq * 2;
            uint32_t hi, lo;
            split2(o[mi][jn][0] * inv0, o[mi][jn][1] * inv0, hi, lo);
            size_t off = (size_t)(b * T_ + t0) * D_ + d;
            *(uint32_t*)&g_ah[off] = hi; *(uint32_t*)&g_al[off] = lo;
            split2(o[mi][jn][2] * inv1, o[mi][jn][3] * inv1, hi, lo);
            off = (size_t)(b * T_ + t1) * D_ + d;
            *(uint32_t*)&g_ah[off] = hi; *(uint32_t*)&g_al[off] = lo;
        }
    }
    CP_WAIT0();
}

// ======================================================================
extern "C" void kernel_launch(void* const* d_in, const int* in_sizes, int n_in,
                              void* d_out, int out_size)
{
    const float* x      = (const float*)d_in[0];
    const float* W_qkv  = (const float*)d_in[1];
    const float* b_qkv  = (const float*)d_in[2];
    const float* W_out  = (const float*)d_in[3];
    const float* b_out  = (const float*)d_in[4];
    float* out = (float*)d_out;

    __nv_bfloat16 *xh, *xl, *ah, *al, *wqh, *wql, *woh, *wol;
    cudaGetSymbolAddress((void**)&xh,  g_xh);
    cudaGetSymbolAddress((void**)&xl,  g_xl);
    cudaGetSymbolAddress((void**)&ah,  g_ah);
    cudaGetSymbolAddress((void**)&al,  g_al);
    cudaGetSymbolAddress((void**)&wqh, g_wqh);
    cudaGetSymbolAddress((void**)&wql, g_wql);
    cudaGetSymbolAddress((void**)&woh, g_woh);
    cudaGetSymbolAddress((void**)&wol, g_wol);

    cudaFuncSetAttribute(gemm_tc_mma, cudaFuncAttributeMaxDynamicSharedMemorySize, SMEM_GT);
    cudaFuncSetAttribute(attn_mma,    cudaFuncAttributeMaxDynamicSharedMemorySize, SMEM_AT);

    const int nX = B_ * T_ * D_;

    conv_split<<<(nX + 255) / 256, 256>>>(x, xh, xl, nX);
    conv_split_tr<<<(D_ * 3 * D_ + 255) / 256, 256>>>(W_qkv, wqh, wql, D_, 3 * D_);
    conv_split_tr<<<(D_ * D_ + 255) / 256, 256>>>(W_out, woh, wol, D_, D_);

    {
        dim3 grid((3 * D_) / 256, (B_ * T_) / 128);
        gemm_tc_mma<<<grid, 256, SMEM_GT>>>(xh, xl, wqh, wql, b_qkv, nullptr,
                                            B_ * T_, 3 * D_, D_, 0);
    }
    {
        dim3 grid(T_ / QT, H_, B_);
        attn_mma<<<grid, 256, SMEM_AT>>>();
    }
    {
        dim3 grid(D_ / 256, (B_ * T_) / 128);
        gemm_tc_mma<<<grid, 256, SMEM_GT>>>(ah, al, woh, wol, b_out, out,
                                            B_ * T_, D_, D_, 1);
    }
}

// round 12
// speedup vs baseline: 1.1128x; 1.1128x over previous
#include <cuda_runtime.h>
#include <cuda_bf16.h>
#include <cstdint>

#define B_   2
#define T_   4096
#define D_   768
#define H_   12
#define HD_  64
#define SCALE_ 0.125f

#define QT 128
#define KT 64

// ---------------- scratch ----------------
__device__ __nv_bfloat16 g_qh[(size_t)B_ * H_ * T_ * HD_];   // [B,H,T,hd]
__device__ __nv_bfloat16 g_ql[(size_t)B_ * H_ * T_ * HD_];
__device__ __nv_bfloat16 g_kh[(size_t)B_ * H_ * T_ * HD_];
__device__ __nv_bfloat16 g_kl[(size_t)B_ * H_ * T_ * HD_];
__device__ __nv_bfloat16 g_vh[(size_t)B_ * H_ * T_ * HD_];   // TRANSPOSED: [B,H,hd,T]
__device__ __nv_bfloat16 g_vl[(size_t)B_ * H_ * T_ * HD_];
__device__ __nv_bfloat16 g_xh[(size_t)B_ * T_ * D_];
__device__ __nv_bfloat16 g_xl[(size_t)B_ * T_ * D_];
__device__ __nv_bfloat16 g_ah[(size_t)B_ * T_ * D_];
__device__ __nv_bfloat16 g_al[(size_t)B_ * T_ * D_];
__device__ __nv_bfloat16 g_wqh[(size_t)3 * D_ * D_];
__device__ __nv_bfloat16 g_wql[(size_t)3 * D_ * D_];
__device__ __nv_bfloat16 g_woh[(size_t)D_ * D_];
__device__ __nv_bfloat16 g_wol[(size_t)D_ * D_];

// ======================= helpers ========================
__device__ __forceinline__ uint32_t smem_u32(const void* p) {
    uint32_t a;
    asm("{ .reg .u64 t; cvta.to.shared.u64 t, %1; cvt.u32.u64 %0, t; }"
        : "=r"(a) : "l"(p));
    return a;
}

__device__ __forceinline__ void cp16(uint32_t s, const void* g) {
    asm volatile("cp.async.cg.shared.global [%0], [%1], 16;" :: "r"(s), "l"(g));
}
#define CP_COMMIT() asm volatile("cp.async.commit_group;" ::: "memory")
#define CP_WAIT1()  asm volatile("cp.async.wait_group 1;" ::: "memory")
#define CP_WAIT0()  asm volatile("cp.async.wait_group 0;" ::: "memory")

__device__ __forceinline__ void mma16816(float* c, const uint32_t* a, const uint32_t* b) {
    asm("mma.sync.aligned.m16n8k16.row.col.f32.bf16.bf16.f32 "
        "{%0,%1,%2,%3}, {%4,%5,%6,%7}, {%8,%9}, {%0,%1,%2,%3};"
        : "+f"(c[0]), "+f"(c[1]), "+f"(c[2]), "+f"(c[3])
        : "r"(a[0]), "r"(a[1]), "r"(a[2]), "r"(a[3]), "r"(b[0]), "r"(b[1]));
}

// ldmatrix x4: loads 4 8x8 bf16 matrices, lane L supplies row address of
// matrix L>>3 (row L&7). Canonical mma fragment distribution on results.
__device__ __forceinline__ void ldsm4(uint32_t& r0, uint32_t& r1,
                                      uint32_t& r2, uint32_t& r3, uint32_t a) {
    asm volatile("ldmatrix.sync.aligned.m8n8.x4.shared.b16 {%0,%1,%2,%3}, [%4];"
                 : "=r"(r0), "=r"(r1), "=r"(r2), "=r"(r3) : "r"(a));
}

__device__ __forceinline__ uint32_t pack_bf(__nv_bfloat16 a, __nv_bfloat16 b) {
    __nv_bfloat162 t(a, b);
    return *reinterpret_cast<uint32_t*>(&t);
}

__device__ __forceinline__ void split2(float v0, float v1, uint32_t& hi, uint32_t& lo) {
    __nv_bfloat16 h0 = __float2bfloat16_rn(v0);
    __nv_bfloat16 h1 = __float2bfloat16_rn(v1);
    float r0 = v0 - __bfloat162float(h0);
    float r1 = v1 - __bfloat162float(h1);
    hi = pack_bf(h0, h1);
    lo = pack_bf(__float2bfloat16_rn(r0), __float2bfloat16_rn(r1));
}

// ======================================================================
// conversions
// ======================================================================
__global__ void conv_split(const float* __restrict__ in,
                           __nv_bfloat16* __restrict__ oh,
                           __nv_bfloat16* __restrict__ ol, int n)
{
    int i = blockIdx.x * blockDim.x + threadIdx.x;
    if (i >= n) return;
    float v = in[i];
    __nv_bfloat16 h = __float2bfloat16_rn(v);
    float r = v - __bfloat162float(h);
    oh[i] = h;
    ol[i] = __float2bfloat16_rn(r);
}

__global__ void conv_split_tr(const float* __restrict__ in,
                              __nv_bfloat16* __restrict__ oh,
                              __nv_bfloat16* __restrict__ ol, int K, int N)
{
    int i = blockIdx.x * blockDim.x + threadIdx.x;
    if (i >= K * N) return;
    int k = i / N, n = i % N;
    float v = in[i];
    __nv_bfloat16 h = __float2bfloat16_rn(v);
    float r = v - __bfloat162float(h);
    oh[(size_t)n * K + k] = h;
    ol[(size_t)n * K + k] = __float2bfloat16_rn(r);
}

// ======================================================================
// HMMA GEMM, bf16 split. Block tile 128(M)x256(N), 256 threads, 8 warps
// in 2(M)x4(N), warp tile 64x64. Fragments via ldmatrix.x4.
// ======================================================================
#define LDKB 144
#define ATILE (128 * LDKB)
#define BTILE (256 * LDKB)
#define BUFSZ (2 * ATILE + 2 * BTILE)
#define AOFF(buf, v) ((buf) * BUFSZ + (v) * ATILE)
#define BOFF(buf, v) ((buf) * BUFSZ + 2 * ATILE + (v) * BTILE)
#define SMEM_GT (2 * BUFSZ)

__global__ void __launch_bounds__(256, 1) gemm_tc_mma(
    const __nv_bfloat16* __restrict__ Ah, const __nv_bfloat16* __restrict__ Al,
    const __nv_bfloat16* __restrict__ Bh, const __nv_bfloat16* __restrict__ Bl,
    const float* __restrict__ bias, float* __restrict__ Cout,
    int M, int N, int K, int mode)
{
    extern __shared__ char smc[];
    const uint32_t sbase = smem_u32(smc);
    const int tid  = threadIdx.x;
    const int lane = tid & 31;
    const int wid  = tid >> 5;
    const int wm   = wid & 1;
    const int wn   = wid >> 1;
    const int bm = blockIdx.y * 128;
    const int bn = blockIdx.x * 256;

    const char* gA[2] = { (const char*)(Ah + (size_t)bm * K),
                          (const char*)(Al + (size_t)bm * K) };
    const char* gB[2] = { (const char*)(Bh + (size_t)bn * K),
                          (const char*)(Bl + (size_t)bn * K) };

    const int nk = K / 64;

    auto issue_chunk = [&](int k0, int buf) {
#pragma unroll
        for (int v = 0; v < 2; v++) {
#pragma unroll
            for (int j = 0; j < 4; j++) {
                const int idx = j * 256 + tid;
                const int row = idx >> 3, c16 = idx & 7;
                cp16(sbase + AOFF(buf, v) + row * LDKB + c16 * 16,
                     gA[v] + (size_t)row * (K * 2) + k0 * 2 + c16 * 16);
            }
#pragma unroll
            for (int j = 0; j < 8; j++) {
                const int idx = j * 256 + tid;
                const int row = idx >> 3, c16 = idx & 7;
                cp16(sbase + BOFF(buf, v) + row * LDKB + c16 * 16,
                     gB[v] + (size_t)row * (K * 2) + k0 * 2 + c16 * 16);
            }
        }
    };

    issue_chunk(0, 0); CP_COMMIT();
    if (nk > 1) { issue_chunk(64, 1); }
    CP_COMMIT();

    float acc[4][8][4];
#pragma unroll
    for (int i = 0; i < 4; i++)
#pragma unroll
        for (int j = 0; j < 8; j++)
#pragma unroll
            for (int q = 0; q < 4; q++) acc[i][j][q] = 0.f;

    const int lr = lane >> 2;
    const int lc = (lane & 3) * 2;

    // ldmatrix per-lane offsets:
    // A x4: m0=(r,+0) m1=(r+8,+0) m2=(r,+16) m3=(r+8,+16)
    const uint32_t aLane = (((lane >> 3) & 1) * 8 + (lane & 7)) * LDKB + (lane >> 4) * 16;
    // B x4 (pair jp -> j=2jp, 2jp+1): m0=(j,+0) m1=(j,+16) m2=(j+1,+0) m3=(j+1,+16)
    const uint32_t bLane = ((lane >> 4) * 8 + (lane & 7)) * LDKB + ((lane >> 3) & 1) * 16;

    for (int it = 0; it < nk; ++it) {
        const int buf = it & 1;
        CP_WAIT1();
        __syncthreads();

        const uint32_t sA[2] = { sbase + AOFF(buf, 0), sbase + AOFF(buf, 1) };
        const uint32_t sB[2] = { sbase + BOFF(buf, 0), sbase + BOFF(buf, 1) };

#pragma unroll
        for (int kk = 0; kk < 4; kk++) {
            uint32_t af[2][4][4];
#pragma unroll
            for (int v = 0; v < 2; v++)
#pragma unroll
                for (int i = 0; i < 4; i++)
                    ldsm4(af[v][i][0], af[v][i][1], af[v][i][2], af[v][i][3],
                          sA[v] + (wm * 64 + i * 16) * LDKB + aLane + kk * 32);
            uint32_t bf[2][8][2];
#pragma unroll
            for (int v = 0; v < 2; v++)
#pragma unroll
                for (int jp = 0; jp < 4; jp++)
                    ldsm4(bf[v][2 * jp][0], bf[v][2 * jp][1],
                          bf[v][2 * jp + 1][0], bf[v][2 * jp + 1][1],
                          sB[v] + (wn * 64 + jp * 16) * LDKB + bLane + kk * 32);
#pragma unroll
            for (int i = 0; i < 4; i++)
#pragma unroll
                for (int j = 0; j < 8; j++)
                    mma16816(acc[i][j], af[0][i], bf[0][j]);
#pragma unroll
            for (int i = 0; i < 4; i++)
#pragma unroll
                for (int j = 0; j < 8; j++)
                    mma16816(acc[i][j], af[0][i], bf[1][j]);
#pragma unroll
            for (int i = 0; i < 4; i++)
#pragma unroll
                for (int j = 0; j < 8; j++)
                    mma16816(acc[i][j], af[1][i], bf[0][j]);
        }
        __syncthreads();
        if (it + 2 < nk) { issue_chunk((it + 2) * 64, buf); }
        CP_COMMIT();
    }

    // -------- epilogue --------
#pragma unroll
    for (int i = 0; i < 4; i++) {
        const int row0 = bm + wm * 64 + i * 16 + lr;
#pragma unroll
        for (int j = 0; j < 8; j++) {
            const int col = bn + wn * 64 + j * 8 + lc;
            const float b0 = bias[col], b1 = bias[col + 1];
            const float v00 = acc[i][j][0] + b0, v01 = acc[i][j][1] + b1;
            const float v10 = acc[i][j][2] + b0, v11 = acc[i][j][3] + b1;
            if (mode == 1) {
                *(float2*)&Cout[(size_t)row0 * N + col]       = make_float2(v00, v01);
                *(float2*)&Cout[(size_t)(row0 + 8) * N + col] = make_float2(v10, v11);
            } else {
                const int sel = col / D_;
                const int rem = col % D_;
                const int h   = rem / HD_;
                const int d0  = rem % HD_;
                const int bb0 = row0 >> 12, t0 = row0 & (T_ - 1);
                const int bb1 = (row0 + 8) >> 12, t1 = (row0 + 8) & (T_ - 1);
                if (sel == 2) {
                    const size_t hb0 = (size_t)(bb0 * H_ + h) * HD_;
                    const size_t hb1 = (size_t)(bb1 * H_ + h) * HD_;
                    __nv_bfloat16 h00 = __float2bfloat16_rn(v00);
                    __nv_bfloat16 h01 = __float2bfloat16_rn(v01);
                    __nv_bfloat16 h10 = __float2bfloat16_rn(v10);
                    __nv_bfloat16 h11 = __float2bfloat16_rn(v11);
                    g_vh[(hb0 + d0)     * T_ + t0] = h00;
                    g_vh[(hb0 + d0 + 1) * T_ + t0] = h01;
                    g_vh[(hb1 + d0)     * T_ + t1] = h10;
                    g_vh[(hb1 + d0 + 1) * T_ + t1] = h11;
                    g_vl[(hb0 + d0)     * T_ + t0] = __float2bfloat16_rn(v00 - __bfloat162float(h00));
                    g_vl[(hb0 + d0 + 1) * T_ + t0] = __float2bfloat16_rn(v01 - __bfloat162float(h01));
                    g_vl[(hb1 + d0)     * T_ + t1] = __float2bfloat16_rn(v10 - __bfloat162float(h10));
                    g_vl[(hb1 + d0 + 1) * T_ + t1] = __float2bfloat16_rn(v11 - __bfloat162float(h11));
                } else {
                    __nv_bfloat16* dh = (sel == 0) ? g_qh : g_kh;
                    __nv_bfloat16* dl = (sel == 0) ? g_ql : g_kl;
                    uint32_t hi, lo;
                    split2(v00, v01, hi, lo);
                    size_t off = ((size_t)(bb0 * H_ + h) * T_ + t0) * HD_ + d0;
                    *(uint32_t*)&dh[off] = hi; *(uint32_t*)&dl[off] = lo;
                    split2(v10, v11, hi, lo);
                    off = ((size_t)(bb1 * H_ + h) * T_ + t1) * HD_ + d0;
                    *(uint32_t*)&dh[off] = hi; *(uint32_t*)&dl[off] = lo;
                }
            }
        }
    }
    CP_WAIT0();
}

// ======================================================================
// Causal flash attention on HMMA, QT=128 (R10 structure), Q hoisted,
// 3-slot cp.async ring, one sync/tile. K/V fragments via ldmatrix.x4.
// ======================================================================
#define APB 144
#define AT_KV  (2 * 128 * APB)           // 36864
#define KVBUF  (4 * 64 * APB)            // 36864 per ring slot
#define SMEM_AT (AT_KV + 3 * KVBUF)      // 147456

__global__ void __launch_bounds__(256, 1) attn_mma()
{
    extern __shared__ char sm[];
    const uint32_t sbase = smem_u32(sm);
    char* sQh = sm;
    char* sQl = sm + 128 * APB;

    const int tid = threadIdx.x, lane = tid & 31, wid = tid >> 5;
    const int lr = lane >> 2, lq = lane & 3;
    const int qi = (int)gridDim.x - 1 - (int)blockIdx.x;
    const int h = blockIdx.y, b = blockIdx.z;
    const int qbase = qi * QT;

    const size_t bh = (size_t)(b * H_ + h) * T_;
    const char* qh = (const char*)(g_qh + (bh + qbase) * HD_);
    const char* ql = (const char*)(g_ql + (bh + qbase) * HD_);
    const char* kh = (const char*)(g_kh + bh * HD_);
    const char* kl = (const char*)(g_kl + bh * HD_);
    const char* vh = (const char*)(g_vh + bh * HD_);   // [hd][T]
    const char* vl = (const char*)(g_vl + bh * HD_);

    auto stage = [&](int kb, int buf) {
        const uint32_t base = sbase + AT_KV + buf * KVBUF;
#pragma unroll
        for (int t = 0; t < 4; t++) {
            const char* src = (t == 0) ? kh : (t == 1) ? kl : (t == 2) ? vh : vl;
#pragma unroll
            for (int j = 0; j < 2; j++) {
                const int idx = j * 256 + tid;
                const int row = idx >> 3, c16 = idx & 7;
                const char* g = (t < 2)
                    ? src + (size_t)(kb + row) * 128 + c16 * 16
                    : src + (size_t)row * (T_ * 2) + (size_t)kb * 2 + c16 * 16;
                cp16(base + t * (64 * APB) + row * APB + c16 * 16, g);
            }
        }
    };

    const int nkt = qbase / KT + 2;

    stage(0, 0); CP_COMMIT();
    stage(KT, 1); CP_COMMIT();

#pragma unroll
    for (int p = 0; p < 4; p++) {
        const int idx = p * 256 + tid;
        const int row = idx >> 3, c16 = idx & 7;
        *(uint4*)(sQh + row * APB + c16 * 16) =
            *(const uint4*)(qh + (size_t)row * 128 + c16 * 16);
        *(uint4*)(sQl + row * APB + c16 * 16) =
            *(const uint4*)(ql + (size_t)row * 128 + c16 * 16);
    }
    __syncthreads();

    // hoist Q fragments: qf[kk][v][4]
    uint32_t qf[4][2][4];
    {
        const int r0 = (wid * 16 + lr) * APB;
#pragma unroll
        for (int kk = 0; kk < 4; kk++) {
            const int kbo = kk * 32 + lq * 4;
            qf[kk][0][0] = *(const uint32_t*)(sQh + r0 + kbo);
            qf[kk][0][1] = *(const uint32_t*)(sQh + r0 + 8 * APB + kbo);
            qf[kk][0][2] = *(const uint32_t*)(sQh + r0 + kbo + 16);
            qf[kk][0][3] = *(const uint32_t*)(sQh + r0 + 8 * APB + kbo + 16);
            qf[kk][1][0] = *(const uint32_t*)(sQl + r0 + kbo);
            qf[kk][1][1] = *(const uint32_t*)(sQl + r0 + 8 * APB + kbo);
            qf[kk][1][2] = *(const uint32_t*)(sQl + r0 + kbo + 16);
            qf[kk][1][3] = *(const uint32_t*)(sQl + r0 + 8 * APB + kbo + 16);
        }
    }

    float m[2] = {-1e30f, -1e30f}, l[2] = {0.f, 0.f};
    float o[8][4];
#pragma unroll
    for (int j = 0; j < 8; j++)
#pragma unroll
        for (int q = 0; q < 4; q++) o[j][q] = 0.f;

    const int rowmaxw = qbase + wid * 16 + 15;

    // ldmatrix per-lane offset for K/V pairs (jp -> rows 2jp*8, (2jp+1)*8)
    const uint32_t kvLane = ((lane >> 4) * 8 + (lane & 7)) * APB + ((lane >> 3) & 1) * 16;

    uint32_t bfh[2][8][2], bfl[2][8][2];

    for (int kt = 0; kt < nkt; kt++) {
        const int kb = kt * KT;
        const int buf = kt % 3;
        const uint32_t kB = sbase + AT_KV + buf * KVBUF;
        const uint32_t klB = kB  + 64 * APB;
        const uint32_t vB  = klB + 64 * APB;
        const uint32_t vlB = vB  + 64 * APB;

        CP_WAIT1();
        __syncthreads();

        if (kt + 2 < nkt) stage((kt + 2) * KT, (kt + 2) % 3);
        CP_COMMIT();

        if (kb > rowmaxw) continue;

        // ---- S = Q K^T (pipelined K frags, ldmatrix) ----
        float s[8][4];
#pragma unroll
        for (int j = 0; j < 8; j++)
#pragma unroll
            for (int q = 0; q < 4; q++) s[j][q] = 0.f;

        auto loadK = [&](int kk, int pb) {
#pragma unroll
            for (int jp = 0; jp < 4; jp++) {
                ldsm4(bfh[pb][2 * jp][0], bfh[pb][2 * jp][1],
                      bfh[pb][2 * jp + 1][0], bfh[pb][2 * jp + 1][1],
                      kB + jp * 16 * APB + kvLane + kk * 32);
                ldsm4(bfl[pb][2 * jp][0], bfl[pb][2 * jp][1],
                      bfl[pb][2 * jp + 1][0], bfl[pb][2 * jp + 1][1],
                      klB + jp * 16 * APB + kvLane + kk * 32);
            }
        };

        loadK(0, 0);
#pragma unroll
        for (int kk = 0; kk < 4; kk++) {
            const int pb = kk & 1;
            if (kk < 3) loadK(kk + 1, pb ^ 1);
#pragma unroll
            for (int j = 0; j < 8; j++) mma16816(s[j], qf[kk][0], bfh[pb][j]);
#pragma unroll
            for (int j = 0; j < 8; j++) mma16816(s[j], qf[kk][0], bfl[pb][j]);
#pragma unroll
            for (int j = 0; j < 8; j++) mma16816(s[j], qf[kk][1], bfh[pb][j]);
        }

        // ---- scale + causal mask ----
        const bool needmask = (kb + 63) > (qbase + wid * 16);
        if (needmask) {
            const int row_a = qbase + wid * 16 + lr;
#pragma unroll
            for (int j = 0; j < 8; j++) {
                const int col0 = kb + j * 8 + lq * 2;
                s[j][0] = (col0     <= row_a)     ? s[j][0] * SCALE_ : -1e30f;
                s[j][1] = (col0 + 1 <= row_a)     ? s[j][1] * SCALE_ : -1e30f;
                s[j][2] = (col0     <= row_a + 8) ? s[j][2] * SCALE_ : -1e30f;
                s[j][3] = (col0 + 1 <= row_a + 8) ? s[j][3] * SCALE_ : -1e30f;
            }
        } else {
#pragma unroll
            for (int j = 0; j < 8; j++)
#pragma unroll
                for (int q = 0; q < 4; q++) s[j][q] *= SCALE_;
        }

        // ---- online softmax ----
#pragma unroll
        for (int r = 0; r < 2; r++) {
            float mx = -1e30f;
#pragma unroll
            for (int j = 0; j < 8; j++)
                mx = fmaxf(mx, fmaxf(s[j][2 * r], s[j][2 * r + 1]));
            mx = fmaxf(mx, __shfl_xor_sync(0xffffffffu, mx, 1));
            mx = fmaxf(mx, __shfl_xor_sync(0xffffffffu, mx, 2));
            const float mnew = fmaxf(m[r], mx);
            const float corr = __expf(m[r] - mnew);
            float sum = 0.f;
#pragma unroll
            for (int j = 0; j < 8; j++) {
                const float p0 = __expf(s[j][2 * r]     - mnew);
                const float p1 = __expf(s[j][2 * r + 1] - mnew);
                s[j][2 * r] = p0; s[j][2 * r + 1] = p1;
                sum += p0 + p1;
            }
            sum += __shfl_xor_sync(0xffffffffu, sum, 1);
            sum += __shfl_xor_sync(0xffffffffu, sum, 2);
            l[r] = l[r] * corr + sum;
            m[r] = mnew;
#pragma unroll
            for (int j = 0; j < 8; j++) {
                o[j][2 * r] *= corr; o[j][2 * r + 1] *= corr;
            }
        }

        // ---- P fragments (split) ----
        uint32_t ph0[8], ph1[8], pl0[8], pl1[8];
#pragma unroll
        for (int j = 0; j < 8; j++) {
            split2(s[j][0], s[j][1], ph0[j], pl0[j]);
            split2(s[j][2], s[j][3], ph1[j], pl1[j]);
        }

        // ---- O += P V (pipelined V frags, ldmatrix) ----
        auto loadV = [&](int kk, int pb) {
#pragma unroll
            for (int jp = 0; jp < 4; jp++) {
                ldsm4(bfh[pb][2 * jp][0], bfh[pb][2 * jp][1],
                      bfh[pb][2 * jp + 1][0], bfh[pb][2 * jp + 1][1],
                      vB + jp * 16 * APB + kvLane + kk * 32);
                ldsm4(bfl[pb][2 * jp][0], bfl[pb][2 * jp][1],
                      bfl[pb][2 * jp + 1][0], bfl[pb][2 * jp + 1][1],
                      vlB + jp * 16 * APB + kvLane + kk * 32);
            }
        };

        loadV(0, 0);
#pragma unroll
        for (int kk = 0; kk < 4; kk++) {
            const int pb = kk & 1;
            if (kk < 3) loadV(kk + 1, pb ^ 1);
            uint32_t a_h[4] = { ph0[2 * kk], ph1[2 * kk], ph0[2 * kk + 1], ph1[2 * kk + 1] };
            uint32_t a_l[4] = { pl0[2 * kk], pl1[2 * kk], pl0[2 * kk + 1], pl1[2 * kk + 1] };
#pragma unroll
            for (int jn = 0; jn < 8; jn++) mma16816(o[jn], a_h, bfh[pb][jn]);
#pragma unroll
            for (int jn = 0; jn < 8; jn++) mma16816(o[jn], a_h, bfl[pb][jn]);
#pragma unroll
            for (int jn = 0; jn < 8; jn++) mma16816(o[jn], a_l, bfh[pb][jn]);
        }
    }

    // ---- epilogue ----
    const float inv0 = 1.f / l[0], inv1 = 1.f / l[1];
    const int t0 = qbase + wid * 16 + lr;
    const int t1 = t0 + 8;
#pragma unroll
    for (int jn = 0; jn < 8; jn++) {
        const int d = h * HD_ + jn * 8 + lq * 2;
        uint32_t hi, lo;
        split2(o[jn][0] * inv0, o[jn][1] * inv0, hi, lo);
        size_t off = (size_t)(b * T_ + t0) * D_ + d;
        *(uint32_t*)&g_ah[off] = hi; *(uint32_t*)&g_al[off] = lo;
        split2(o[jn][2] * inv1, o[jn][3] * inv1, hi, lo);
        off = (size_t)(b * T_ + t1) * D_ + d;
        *(uint32_t*)&g_ah[off] = hi; *(uint32_t*)&g_al[off] = lo;
    }
    CP_WAIT0();
}

// ======================================================================
extern "C" void kernel_launch(void* const* d_in, const int* in_sizes, int n_in,
                              void* d_out, int out_size)
{
    const float* x      = (const float*)d_in[0];
    const float* W_qkv  = (const float*)d_in[1];
    const float* b_qkv  = (const float*)d_in[2];
    const float* W_out  = (const float*)d_in[3];
    const float* b_out  = (const float*)d_in[4];
    float* out = (float*)d_out;

    __nv_bfloat16 *xh, *xl, *ah, *al, *wqh, *wql, *woh, *wol;
    cudaGetSymbolAddress((void**)&xh,  g_xh);
    cudaGetSymbolAddress((void**)&xl,  g_xl);
    cudaGetSymbolAddress((void**)&ah,  g_ah);
    cudaGetSymbolAddress((void**)&al,  g_al);
    cudaGetSymbolAddress((void**)&wqh, g_wqh);
    cudaGetSymbolAddress((void**)&wql, g_wql);
    cudaGetSymbolAddress((void**)&woh, g_woh);
    cudaGetSymbolAddress((void**)&wol, g_wol);

    cudaFuncSetAttribute(gemm_tc_mma, cudaFuncAttributeMaxDynamicSharedMemorySize, SMEM_GT);
    cudaFuncSetAttribute(attn_mma,    cudaFuncAttributeMaxDynamicSharedMemorySize, SMEM_AT);

    const int nX = B_ * T_ * D_;

    conv_split<<<(nX + 255) / 256, 256>>>(x, xh, xl, nX);
    conv_split_tr<<<(D_ * 3 * D_ + 255) / 256, 256>>>(W_qkv, wqh, wql, D_, 3 * D_);
    conv_split_tr<<<(D_ * D_ + 255) / 256, 256>>>(W_out, woh, wol, D_, D_);

    {
        dim3 grid((3 * D_) / 256, (B_ * T_) / 128);
        gemm_tc_mma<<<grid, 256, SMEM_GT>>>(xh, xl, wqh, wql, b_qkv, nullptr,
                                            B_ * T_, 3 * D_, D_, 0);
    }
    {
        dim3 grid(T_ / QT, H_, B_);
        attn_mma<<<grid, 256, SMEM_AT>>>();
    }
    {
        dim3 grid(D_ / 256, (B_ * T_) / 128);
        gemm_tc_mma<<<grid, 256, SMEM_GT>>>(ah, al, woh, wol, b_out, out,
                                            B_ * T_, D_, D_, 1);
    }
}